// round 15
// baseline (speedup 1.0000x reference)
#include <cuda_runtime.h>
#include <cstdint>
#include <cstddef>

#define Bn 256
#define Tn 2048
#define Nn 17
#define En 8
#define An 4
#define Mn 2
#define Hn 768
#define FULL 0xffffffffu
// 3 time-segments (transition space t=1..2047):
//  seg1 [1..679] fwd a1 (true init at t=0); seg2 [680..1359] fwd a2 + bwd b2;
//  seg3 [1360..2047] bwd b3.
// den = s0 + ln2(La1+Lb2+Lb3) + ln(b2.a1) + ln(b3.a2) - ln(sum a2)

__device__ float g_trans[Nn * Nn];
__device__ float g_E[Nn * Nn];
__device__ float g_scratch[Bn];
__device__ int g_done;

// ---------------------------------------------------------------------------
// Kernel 1: build transition matrix (17x17) and its elementwise exp.
// ---------------------------------------------------------------------------
__global__ void k_build(const float* __restrict__ hiddens,
                        const float* __restrict__ p_in,
                        const float* __restrict__ p_cross,
                        const float* __restrict__ p_out,
                        const float* __restrict__ p_to_out,
                        const float* __restrict__ p_from_out,
                        const float* __restrict__ w_attn,
                        const float* __restrict__ b_attn) {
    __shared__ float att[En][An];
    __shared__ float wT[An][Hn];
    int tid = threadIdx.x;
    int wid = tid >> 5, lane = tid & 31;
    if (tid == 0) g_done = 0;
    for (int idx = tid; idx < Hn * An; idx += 1024) {
        int h = idx / An, a = idx % An;
        wT[a][h] = w_attn[idx];
    }
    __syncthreads();
    if (wid < En * An) {
        int e = wid / An, a = wid % An;
        float s = 0.f;
        for (int h = lane; h < Hn; h += 32)
            s = fmaf(hiddens[e * Hn + h], wT[a][h], s);
#pragma unroll
        for (int off = 16; off; off >>= 1) s += __shfl_xor_sync(FULL, s, off);
        if (lane == 0) att[e][a] = s + b_attn[a];
    }
    __syncthreads();
    if (tid < An) {
        int a = tid;
        float col[En], mx = -3.4e38f;
        for (int e = 0; e < En; e++) { col[e] = att[e][a]; mx = fmaxf(mx, col[e]); }
        float sm = 0.f;
        for (int e = 0; e < En; e++) { col[e] = expf(col[e] - mx); sm += col[e]; }
        for (int e = 0; e < En; e++) att[e][a] = col[e] / sm;
    }
    __syncthreads();
    if (tid < En) {
        int e = tid;
        float row[An], mx = -3.4e38f;
        for (int a = 0; a < An; a++) { row[a] = att[e][a] * 10.f; mx = fmaxf(mx, row[a]); }
        float sm = 0.f;
        for (int a = 0; a < An; a++) { row[a] = expf(row[a] - mx); sm += row[a]; }
        for (int a = 0; a < An; a++) att[e][a] = row[a] / sm;
    }
    __syncthreads();
    if (tid < Nn * Nn) {
        int r = tid / Nn, c = tid % Nn;
        float v;
        if (r == 0 && c == 0) {
            v = p_out[0];
        } else if (r == 0) {
            v = p_from_out[(c - 1) % Mn];
        } else if (c == 0) {
            v = p_to_out[(r - 1) % Mn];
        } else {
            int e = (r - 1) / Mn, m = (r - 1) % Mn;
            int f = (c - 1) / Mn, mp = (c - 1) % Mn;
            if (e == f) {
                float s2 = 0.f;
                for (int a = 0; a < An; a++)
                    s2 = fmaf(p_in[a * Mn * Mn + m * Mn + mp], att[e][a], s2);
                v = s2 * (1.0f / An);
            } else {
                v = p_cross[m * Mn + mp];
            }
        }
        g_trans[tid] = v;
        g_E[tid] = expf(v);
    }
}

// ---------------------------------------------------------------------------
// Kernel 2: 5 warps per batch, paired-step chains (2 transitions per smem
// round-trip). Full intermediate vector computed in-lane via the block
// structure of E (R6-validated), then one own-column step. exp(emit) rows for
// full-steps come from a self-produced smem ring (written one block ahead).
// ---------------------------------------------------------------------------
__global__ void __launch_bounds__(160, 2)
k_scan(const float* __restrict__ inputs,
       const int* __restrict__ tags,
       const int* __restrict__ mask,
       float* __restrict__ out) {
    int b = blockIdx.x;
    int wid = threadIdx.x >> 5;
    int j = threadIdx.x & 31;
    bool act = (j < Nn);

    __shared__ float s_tr[Nn * Nn];
    __shared__ __align__(16) float wb[4][2][20];
    __shared__ __align__(16) float rg[4][2][8][20];   // exp(emit) rings
    __shared__ __align__(16) float s_vec[4][20];      // 0=a1,1=a2,2=b2,3=b3
    __shared__ double s_l2[4];
    __shared__ float s_s0, s_num;

    for (int idx = threadIdx.x; idx < Nn * Nn; idx += 160) s_tr[idx] = g_trans[idx];
    __syncthreads();

    const float* inp = inputs + (size_t)b * Tn * Nn;
    const int* tgp = tags + (size_t)b * Tn;
    const int* mkp = mask + (size_t)b * Tn;

    if (wid < 4) {
        // shared structured constants (broadcast loads, all lanes same)
        float EO = g_E[0], FO0 = g_E[1], FO1 = g_E[2];
        float TO0 = g_E[Nn], TO1 = g_E[2 * Nn];
        float C00 = g_E[1 * Nn + 3], C01 = g_E[1 * Nn + 4];
        float C10 = g_E[2 * Nn + 3], C11 = g_E[2 * Nn + 4];
        float D00[8], D01[8], D10[8], D11[8];
#pragma unroll
        for (int f = 0; f < 8; f++) {
            int r0 = (1 + 2 * f) * Nn, r1 = (2 + 2 * f) * Nn;
            int c0 = 1 + 2 * f, c1 = 2 + 2 * f;
            D00[f] = g_E[r0 + c0] - C00;
            D01[f] = g_E[r0 + c1] - C01;
            D10[f] = g_E[r1 + c0] - C10;
            D11[f] = g_E[r1 + c1] - C11;
        }

        if (wid < 2) {
            // ======== FORWARD: cw=0 seg1 [0..679], cw=1 seg2 [680..1359] ========
            int cw = wid;
            int tb0 = (cw == 0) ? 0 : 680;
            const int NBLK = 85;
            float Ec[Nn];
#pragma unroll
            for (int i = 0; i < Nn; i++) Ec[i] = act ? g_E[i * Nn + j] : 0.f;

            float rA[8], rB[8]; int mA[8], mB[8]; float ew[8];
#pragma unroll
            for (int u = 0; u < 8; u++) {
                rA[u] = act ? __ldg(inp + (size_t)(tb0 + u) * Nn + j) : 0.f;
                mA[u] = __ldg(mkp + tb0 + u);
            }
#pragma unroll
            for (int u = 0; u < 8; u++) ew[u] = __expf(rA[u]);
            // ring for block 0 (even offsets)
            if (act) {
#pragma unroll
                for (int u = 0; u < 8; u += 2) rg[cw][0][u >> 1][j] = ew[u];
            }

            float w, s0 = 0.f;
            double l2 = 0.0;
            if (cw == 0) {
                float r0v = rA[0];
                s0 = __shfl_sync(FULL, r0v, 0);
                w = act ? __expf(r0v - s0) : 0.f;
            } else {
                w = act ? 1.f : 0.f;
            }
            if (act) { wb[cw][0][j] = w; wb[cw][1][j] = w; }
            __syncwarp();

            for (int blk = 0; blk < NBLK; blk++) {
                if (blk + 1 < NBLK) {
                    int tp = tb0 + (blk + 1) * 8;
#pragma unroll
                    for (int u = 0; u < 8; u++) {
                        rB[u] = act ? __ldg(inp + (size_t)(tp + u) * Nn + j) : 0.f;
                        mB[u] = __ldg(mkp + tp + u);
                    }
                }
#pragma unroll
                for (int r = 0; r < 4; r++) {
                    __syncwarp();
                    const float* wsrc = &wb[cw][(r + 1) & 1][0];
                    float4 v0 = *(const float4*)(wsrc + 0);
                    float4 v1 = *(const float4*)(wsrc + 4);
                    float4 v2 = *(const float4*)(wsrc + 8);
                    float4 v3 = *(const float4*)(wsrc + 12);
                    float vv16 = wsrc[16];
                    const float* esrc = &rg[cw][blk & 1][r][0];
                    float4 e0 = *(const float4*)(esrc + 0);
                    float4 e1 = *(const float4*)(esrc + 4);
                    float4 e2 = *(const float4*)(esrc + 8);
                    float4 e3 = *(const float4*)(esrc + 12);
                    float ee16 = esrc[16];
                    float vv[17] = {v0.x, v0.y, v0.z, v0.w, v1.x, v1.y, v1.z, v1.w,
                                    v2.x, v2.y, v2.z, v2.w, v3.x, v3.y, v3.z, v3.w, vv16};
                    float ea[17] = {e0.x, e0.y, e0.z, e0.w, e1.x, e1.y, e1.z, e1.w,
                                    e2.x, e2.y, e2.z, e2.w, e3.x, e3.y, e3.z, e3.w, ee16};
                    bool skipa = (cw == 0 && blk == 0 && r == 0);
                    int ma = mA[2 * r], mb = mA[2 * r + 1];
                    float wm[17];
                    if (skipa || ma == 0) {
#pragma unroll
                        for (int i = 0; i < 17; i++) wm[i] = vv[i];
                    } else {
                        float S0 = ((vv[1] + vv[3]) + (vv[5] + vv[7]))
                                 + ((vv[9] + vv[11]) + (vv[13] + vv[15]));
                        float S1 = ((vv[2] + vv[4]) + (vv[6] + vv[8]))
                                 + ((vv[10] + vv[12]) + (vv[14] + vv[16]));
                        float U0 = fmaf(C10, S1, C00 * S0);
                        float U1 = fmaf(C11, S1, C01 * S0);
                        float V0 = fmaf(FO0, vv[0], U0);
                        float V1 = fmaf(FO1, vv[0], U1);
                        wm[0] = ea[0] * fmaf(TO1, S1, fmaf(TO0, S0, EO * vv[0]));
#pragma unroll
                        for (int f = 0; f < 8; f++) {
                            float b0 = vv[1 + 2 * f], b1 = vv[2 + 2 * f];
                            wm[1 + 2 * f] = ea[1 + 2 * f] * fmaf(D10[f], b1, fmaf(D00[f], b0, V0));
                            wm[2 + 2 * f] = ea[2 + 2 * f] * fmaf(D11[f], b1, fmaf(D01[f], b0, V1));
                        }
                    }
                    // own-column step (t_b) with ee_b = ew[2r+1]
                    float acc0 = wm[0] * Ec[0], acc1 = wm[1] * Ec[1];
                    float acc2 = wm[2] * Ec[2], acc3 = wm[3] * Ec[3];
                    acc0 = fmaf(wm[4], Ec[4], acc0);   acc1 = fmaf(wm[5], Ec[5], acc1);
                    acc2 = fmaf(wm[6], Ec[6], acc2);   acc3 = fmaf(wm[7], Ec[7], acc3);
                    acc0 = fmaf(wm[8], Ec[8], acc0);   acc1 = fmaf(wm[9], Ec[9], acc1);
                    acc2 = fmaf(wm[10], Ec[10], acc2); acc3 = fmaf(wm[11], Ec[11], acc3);
                    acc0 = fmaf(wm[12], Ec[12], acc0); acc1 = fmaf(wm[13], Ec[13], acc1);
                    acc2 = fmaf(wm[14], Ec[14], acc2); acc3 = fmaf(wm[15], Ec[15], acc3);
                    acc0 = fmaf(wm[16], Ec[16], acc0);
                    float wn = ew[2 * r + 1] * ((acc0 + acc1) + (acc2 + acc3));
                    float wown = act ? wm[j] : 0.f;
                    w = (mb > 0) ? wn : wown;
                    if (r == 3) {                 // renorm once per block
                        float sc = vv[0];
                        w *= __frcp_rn(sc);
                        l2 += (double)__log2f(sc);
                    }
                    if (act) wb[cw][r & 1][j] = w;
                }
                // rotate + ring for next block
#pragma unroll
                for (int u = 0; u < 8; u++) ew[u] = __expf(rB[u]);
                if (act) {
#pragma unroll
                    for (int u = 0; u < 8; u += 2) rg[cw][(blk + 1) & 1][u >> 1][j] = ew[u];
                }
#pragma unroll
                for (int u = 0; u < 8; u++) { rA[u] = rB[u]; mA[u] = mB[u]; }
            }
            if (act) s_vec[cw][j] = w;
            if (j == 0) { s_l2[cw] = l2; if (cw == 0) s_s0 = s0; }
        } else {
            // ======== BACKWARD: cw=2 seg2 [1359..680], cw=3 seg3 [2047..1360] ====
            int cw = wid;
            int thi = (cw == 2) ? 1359 : 2047;
            int tlo = (cw == 2) ? 680 : 1360;
            int NB = (thi - tlo + 1) / 8;       // 85 or 86
            float Fr[Nn];
#pragma unroll
            for (int i = 0; i < Nn; i++) Fr[i] = act ? g_E[j * Nn + i] : 0.f;

            float rA[8], rB[8]; int mA[8], mB[8]; float ew[8];
            int tbA = thi - 7;
#pragma unroll
            for (int u = 0; u < 8; u++) {
                rA[u] = act ? __ldg(inp + (size_t)(tbA + u) * Nn + j) : 0.f;
                mA[u] = __ldg(mkp + tbA + u);
            }
#pragma unroll
            for (int u = 0; u < 8; u++) ew[u] = __expf(rA[u]);
            if (act) {
#pragma unroll
                for (int u = 0; u < 8; u++) rg[cw][0][u][j] = ew[u];
            }

            float ur = act ? 1.f : 0.f;
            double l2 = 0.0;

            for (int k = 0; k < NB; k++) {
                int tb = tbA - 8 * k;
                if (tb - 8 >= tlo) {
                    int tp = tb - 8;
#pragma unroll
                    for (int u = 0; u < 8; u++) {
                        rB[u] = act ? __ldg(inp + (size_t)(tp + u) * Nn + j) : 0.f;
                        mB[u] = __ldg(mkp + tp + u);
                    }
                }
#pragma unroll
                for (int r = 3; r >= 0; r--) {
                    if (act) wb[cw][r & 1][j] = ur;
                    __syncwarp();
                    const float* usrc = &wb[cw][r & 1][0];
                    float4 v0 = *(const float4*)(usrc + 0);
                    float4 v1 = *(const float4*)(usrc + 4);
                    float4 v2 = *(const float4*)(usrc + 8);
                    float4 v3 = *(const float4*)(usrc + 12);
                    float q16 = usrc[16];
                    const float* eb_s = &rg[cw][k & 1][2 * r + 1][0];
                    float4 f0 = *(const float4*)(eb_s + 0);
                    float4 f1 = *(const float4*)(eb_s + 4);
                    float4 f2 = *(const float4*)(eb_s + 8);
                    float4 f3 = *(const float4*)(eb_s + 12);
                    float fb16 = eb_s[16];
                    const float* ea_s = &rg[cw][k & 1][2 * r][0];
                    float4 g0 = *(const float4*)(ea_s + 0);
                    float4 g1 = *(const float4*)(ea_s + 4);
                    float4 g2 = *(const float4*)(ea_s + 8);
                    float4 g3 = *(const float4*)(ea_s + 12);
                    float ga16 = ea_s[16];
                    float q[17] = {v0.x, v0.y, v0.z, v0.w, v1.x, v1.y, v1.z, v1.w,
                                   v2.x, v2.y, v2.z, v2.w, v3.x, v3.y, v3.z, v3.w, q16};
                    float eb[17] = {f0.x, f0.y, f0.z, f0.w, f1.x, f1.y, f1.z, f1.w,
                                    f2.x, f2.y, f2.z, f2.w, f3.x, f3.y, f3.z, f3.w, fb16};
                    float ea[17] = {g0.x, g0.y, g0.z, g0.w, g1.x, g1.y, g1.z, g1.w,
                                    g2.x, g2.y, g2.z, g2.w, g3.x, g3.y, g3.z, g3.w, ga16};
                    int mb = mA[2 * r + 1], ma = mA[2 * r];
                    float um[17];
                    if (mb == 0) {
#pragma unroll
                        for (int i = 0; i < 17; i++) um[i] = q[i];
                    } else {
                        float z[17];
#pragma unroll
                        for (int i = 0; i < 17; i++) z[i] = eb[i] * q[i];
                        float Z0 = ((z[1] + z[3]) + (z[5] + z[7]))
                                 + ((z[9] + z[11]) + (z[13] + z[15]));
                        float Z1 = ((z[2] + z[4]) + (z[6] + z[8]))
                                 + ((z[10] + z[12]) + (z[14] + z[16]));
                        float W0 = fmaf(TO0, z[0], fmaf(C01, Z1, C00 * Z0));
                        float W1 = fmaf(TO1, z[0], fmaf(C11, Z1, C10 * Z0));
                        um[0] = fmaf(FO1, Z1, fmaf(FO0, Z0, EO * z[0]));
#pragma unroll
                        for (int e = 0; e < 8; e++) {
                            float z0e = z[1 + 2 * e], z1e = z[2 + 2 * e];
                            um[1 + 2 * e] = fmaf(D01[e], z1e, fmaf(D00[e], z0e, W0));
                            um[2 + 2 * e] = fmaf(D11[e], z1e, fmaf(D10[e], z0e, W1));
                        }
                    }
                    float za[17];
#pragma unroll
                    for (int i = 0; i < 17; i++) za[i] = ea[i] * um[i];
                    float acc0 = za[0] * Fr[0], acc1 = za[1] * Fr[1];
                    float acc2 = za[2] * Fr[2], acc3 = za[3] * Fr[3];
                    acc0 = fmaf(za[4], Fr[4], acc0);   acc1 = fmaf(za[5], Fr[5], acc1);
                    acc2 = fmaf(za[6], Fr[6], acc2);   acc3 = fmaf(za[7], Fr[7], acc3);
                    acc0 = fmaf(za[8], Fr[8], acc0);   acc1 = fmaf(za[9], Fr[9], acc1);
                    acc2 = fmaf(za[10], Fr[10], acc2); acc3 = fmaf(za[11], Fr[11], acc3);
                    acc0 = fmaf(za[12], Fr[12], acc0); acc1 = fmaf(za[13], Fr[13], acc1);
                    acc2 = fmaf(za[14], Fr[14], acc2); acc3 = fmaf(za[15], Fr[15], acc3);
                    acc0 = fmaf(za[16], Fr[16], acc0);
                    float un = (acc0 + acc1) + (acc2 + acc3);
                    float uown = act ? um[j] : 0.f;
                    ur = (ma > 0) ? un : uown;
                    if (r == 0) {                 // renorm once per block
                        float sc = q[0];
                        ur *= __frcp_rn(sc);
                        l2 += (double)__log2f(sc);
                    }
                }
#pragma unroll
                for (int u = 0; u < 8; u++) ew[u] = __expf(rB[u]);
                if (act) {
#pragma unroll
                    for (int u = 0; u < 8; u++) rg[cw][(k + 1) & 1][u][j] = ew[u];
                }
#pragma unroll
                for (int u = 0; u < 8; u++) { rA[u] = rB[u]; mA[u] = mB[u]; }
            }
            if (act) s_vec[cw][j] = ur;
            if (j == 0) s_l2[cw] = l2;
        }
    } else {
        // ===================== NUMERATOR =====================
        float tr_acc = 0.f, em_acc = 0.f;
        int cnt = 0;
        for (int t = j; t < Tn - 1; t += 32) {
            int tg0 = __ldg(tgp + t), tg1 = __ldg(tgp + t + 1);
            int mk0 = __ldg(mkp + t), mk1 = __ldg(mkp + t + 1);
            float ev = __ldg(inp + (size_t)t * Nn + tg0);
            tr_acc = fmaf(s_tr[tg0 * Nn + tg1], (float)mk1, tr_acc);
            em_acc = fmaf(ev, (float)mk0, em_acc);
            cnt += mk0;
        }
#pragma unroll
        for (int off = 16; off; off >>= 1) {
            tr_acc += __shfl_xor_sync(FULL, tr_acc, off);
            em_acc += __shfl_xor_sync(FULL, em_acc, off);
            cnt += __shfl_xor_sync(FULL, cnt, off);
        }
        if (j == 0) {
            int mkL = __ldg(mkp + Tn - 1);
            cnt += mkL;
            int li = cnt - 1; if (li < 0) li = 0;
            int tagL = __ldg(tgp + li);
            float evL = __ldg(inp + (size_t)(Tn - 1) * Nn + tagL) * (float)mkL;
            s_num = tr_acc + em_acc + evL;
        }
    }
    __syncthreads();

    if (wid == 0) {
        // ---- combine: den = s0 + ln2(La1+Lb2+Lb3) + ln(b2.a1)+ln(b3.a2)-ln(sum a2)
        float d1 = act ? s_vec[2][j] * s_vec[0][j] : 0.f;
        float d2 = act ? s_vec[3][j] * s_vec[1][j] : 0.f;
        float m2 = act ? s_vec[1][j] : 0.f;
#pragma unroll
        for (int off = 16; off; off >>= 1) {
            d1 += __shfl_xor_sync(FULL, d1, off);
            d2 += __shfl_xor_sync(FULL, d2, off);
            m2 += __shfl_xor_sync(FULL, m2, off);
        }
        if (j == 0) {
            double l2t = s_l2[0] + s_l2[2] + s_l2[3];
            double den = (double)s_s0 + 0.6931471805599453 * l2t
                       + log((double)d1) + log((double)d2) - log((double)m2);
            g_scratch[b] = (float)((double)s_num - den);
            __threadfence();
        }
        int flag = 0;
        if (j == 0) {
            int ticket = atomicAdd(&g_done, 1);
            flag = (ticket == Bn - 1);
        }
        flag = __shfl_sync(FULL, flag, 0);
        if (flag) {
            __threadfence();
            volatile float* gs = g_scratch;
            double acc = 0.0;
#pragma unroll
            for (int k = 0; k < Bn / 32; k++) acc += (double)gs[j + k * 32];
#pragma unroll
            for (int off = 16; off; off >>= 1) acc += __shfl_xor_sync(FULL, acc, off);
            if (j == 0) out[0] = (float)acc;
        }
    }
}

extern "C" void kernel_launch(void* const* d_in, const int* in_sizes, int n_in,
                              void* d_out, int out_size) {
    const float* inputs     = (const float*)d_in[0];
    const int*   tags       = (const int*)d_in[1];
    const float* hiddens    = (const float*)d_in[2];
    const int*   mask       = (const int*)d_in[3];
    const float* p_in       = (const float*)d_in[4];
    const float* p_cross    = (const float*)d_in[5];
    const float* p_out      = (const float*)d_in[6];
    const float* p_to_out   = (const float*)d_in[7];
    const float* p_from_out = (const float*)d_in[8];
    const float* w_attn     = (const float*)d_in[9];
    const float* b_attn     = (const float*)d_in[10];

    k_build<<<1, 1024>>>(hiddens, p_in, p_cross, p_out, p_to_out, p_from_out,
                         w_attn, b_attn);
    k_scan<<<Bn, 160>>>(inputs, tags, mask, (float*)d_out);
}

// round 16
// speedup vs baseline: 1.9690x; 1.9690x over previous
#include <cuda_runtime.h>
#include <cstdint>
#include <cstddef>

#define Bn 256
#define Tn 2048
#define Nn 17
#define En 8
#define An 4
#define Mn 2
#define Hn 768
#define FULL 0xffffffffu
// 3 time-segments (transition space t=1..2047):
//  seg1 [1..679] fwd a1 (true init at t=0); seg2 [680..1359] fwd a2 + bwd b2;
//  seg3 [1360..2047] bwd b3.
// den = s0 + ln2(La1+Lb2+Lb3) + ln(b2.a1) + ln(b3.a2) - ln(sum a2)

__device__ float g_trans[Nn * Nn];
__device__ float g_E[Nn * Nn];
__device__ float g_scratch[Bn];
__device__ int g_done;

// ---------------------------------------------------------------------------
// Kernel 1: build transition matrix (17x17) and its elementwise exp.
// w_attn staged transposed in smem so the H-reduction is fully coalesced.
// ---------------------------------------------------------------------------
__global__ void k_build(const float* __restrict__ hiddens,
                        const float* __restrict__ p_in,
                        const float* __restrict__ p_cross,
                        const float* __restrict__ p_out,
                        const float* __restrict__ p_to_out,
                        const float* __restrict__ p_from_out,
                        const float* __restrict__ w_attn,
                        const float* __restrict__ b_attn) {
    __shared__ float att[En][An];
    __shared__ float wT[An][Hn];      // transposed w_attn (12 KB)
    int tid = threadIdx.x;
    int wid = tid >> 5, lane = tid & 31;
    if (tid == 0) g_done = 0;
    for (int idx = tid; idx < Hn * An; idx += 1024) {
        int h = idx / An, a = idx % An;
        wT[a][h] = w_attn[idx];
    }
    __syncthreads();
    if (wid < En * An) {
        int e = wid / An, a = wid % An;
        float s = 0.f;
        for (int h = lane; h < Hn; h += 32)
            s = fmaf(hiddens[e * Hn + h], wT[a][h], s);
#pragma unroll
        for (int off = 16; off; off >>= 1) s += __shfl_xor_sync(FULL, s, off);
        if (lane == 0) att[e][a] = s + b_attn[a];
    }
    __syncthreads();
    if (tid < An) {
        int a = tid;
        float col[En], mx = -3.4e38f;
        for (int e = 0; e < En; e++) { col[e] = att[e][a]; mx = fmaxf(mx, col[e]); }
        float sm = 0.f;
        for (int e = 0; e < En; e++) { col[e] = expf(col[e] - mx); sm += col[e]; }
        for (int e = 0; e < En; e++) att[e][a] = col[e] / sm;
    }
    __syncthreads();
    if (tid < En) {
        int e = tid;
        float row[An], mx = -3.4e38f;
        for (int a = 0; a < An; a++) { row[a] = att[e][a] * 10.f; mx = fmaxf(mx, row[a]); }
        float sm = 0.f;
        for (int a = 0; a < An; a++) { row[a] = expf(row[a] - mx); sm += row[a]; }
        for (int a = 0; a < An; a++) att[e][a] = row[a] / sm;
    }
    __syncthreads();
    if (tid < Nn * Nn) {
        int r = tid / Nn, c = tid % Nn;
        float v;
        if (r == 0 && c == 0) {
            v = p_out[0];
        } else if (r == 0) {
            v = p_from_out[(c - 1) % Mn];
        } else if (c == 0) {
            v = p_to_out[(r - 1) % Mn];
        } else {
            int e = (r - 1) / Mn, m = (r - 1) % Mn;
            int f = (c - 1) / Mn, mp = (c - 1) % Mn;
            if (e == f) {
                float s2 = 0.f;
                for (int a = 0; a < An; a++)
                    s2 = fmaf(p_in[a * Mn * Mn + m * Mn + mp], att[e][a], s2);
                v = s2 * (1.0f / An);
            } else {
                v = p_cross[m * Mn + mp];
            }
        }
        g_trans[tid] = v;
        g_E[tid] = expf(v);
    }
}

// ---------------------------------------------------------------------------
// Kernel 2: 5 warps per batch (3-segment rank-1 decomposition), R11 protocol:
//  w0: fwd a1 over seg1 (true init)   w1: fwd a2 over seg2 (probe ones)
//  w2: bwd b2 over seg2 (probe ones)  w3: bwd b3 over seg3 (probe ones)
//  w4: numerator. Block prefetch (blk+2), syncwarp ping-pong, free renorm.
// ---------------------------------------------------------------------------
__global__ void __launch_bounds__(160, 2)
k_scan(const float* __restrict__ inputs,
       const int* __restrict__ tags,
       const int* __restrict__ mask,
       float* __restrict__ out) {
    int b = blockIdx.x;
    int wid = threadIdx.x >> 5;
    int j = threadIdx.x & 31;
    bool act = (j < Nn);

    __shared__ float s_tr[Nn * Nn];
    __shared__ __align__(16) float wb[4][2][20];
    __shared__ __align__(16) float s_vec[4][20];   // 0=a1, 1=a2, 2=b2, 3=b3
    __shared__ double s_l2[4];
    __shared__ float s_s0, s_num;

    for (int idx = threadIdx.x; idx < Nn * Nn; idx += 160) s_tr[idx] = g_trans[idx];
    __syncthreads();

    const float* inp = inputs + (size_t)b * Tn * Nn;
    const int* tgp = tags + (size_t)b * Tn;
    const int* mkp = mask + (size_t)b * Tn;

    if (wid < 2) {
        // ============ FORWARD chain: cw=0 seg1 [t=0..679], cw=1 seg2 [680..1359]
        int cw = wid;
        int tb0 = (cw == 0) ? 0 : 680;
        const int NBLK = 85;
        float E0  = act ? g_E[0 * Nn + j]  : 0.f, E1  = act ? g_E[1 * Nn + j]  : 0.f;
        float E2  = act ? g_E[2 * Nn + j]  : 0.f, E3  = act ? g_E[3 * Nn + j]  : 0.f;
        float E4  = act ? g_E[4 * Nn + j]  : 0.f, E5  = act ? g_E[5 * Nn + j]  : 0.f;
        float E6  = act ? g_E[6 * Nn + j]  : 0.f, E7  = act ? g_E[7 * Nn + j]  : 0.f;
        float E8  = act ? g_E[8 * Nn + j]  : 0.f, E9  = act ? g_E[9 * Nn + j]  : 0.f;
        float E10 = act ? g_E[10 * Nn + j] : 0.f, E11 = act ? g_E[11 * Nn + j] : 0.f;
        float E12 = act ? g_E[12 * Nn + j] : 0.f, E13 = act ? g_E[13 * Nn + j] : 0.f;
        float E14 = act ? g_E[14 * Nn + j] : 0.f, E15 = act ? g_E[15 * Nn + j] : 0.f;
        float E16 = act ? g_E[16 * Nn + j] : 0.f;

        float rA[8], rB[8], rC[8];
        int mA[8], mB[8], mC[8];
        float ew[8];
#pragma unroll
        for (int u = 0; u < 8; u++) {
            rA[u] = act ? __ldg(inp + (size_t)(tb0 + u) * Nn + j) : 0.f;
            mA[u] = __ldg(mkp + tb0 + u);
            rB[u] = act ? __ldg(inp + (size_t)(tb0 + 8 + u) * Nn + j) : 0.f;
            mB[u] = __ldg(mkp + tb0 + 8 + u);
            rC[u] = 0.f; mC[u] = 0;
        }
#pragma unroll
        for (int u = 0; u < 8; u++) ew[u] = __expf(rA[u]);

        float w, s0 = 0.f;
        double l2 = 0.0;
        if (cw == 0) {      // true init: alpha0 = emit(t=0)
            float r0v = rA[0];
            s0 = __shfl_sync(FULL, r0v, 0);
            w = act ? __expf(r0v - s0) : 0.f;
        } else {            // rank-1 probe from ones
            w = act ? 1.f : 0.f;
        }
        // init both ping-pong slots (first executed step reads slot (u+1)&1)
        if (act) { wb[cw][0][j] = w; wb[cw][1][j] = w; }
        __syncwarp();

        for (int blk = 0; blk < NBLK; blk++) {
            if (blk + 2 < NBLK) {
                int tp = tb0 + (blk + 2) * 8;
#pragma unroll
                for (int u = 0; u < 8; u++) {
                    rC[u] = act ? __ldg(inp + (size_t)(tp + u) * Nn + j) : 0.f;
                    mC[u] = __ldg(mkp + tp + u);
                }
            }
#pragma unroll
            for (int u = 0; u < 8; u++) {
                if (cw == 0 && blk == 0 && u == 0) continue;   // t=0 in init
                __syncwarp();
                float4 v0 = *(const float4*)&wb[cw][(u + 1) & 1][0];
                float4 v1 = *(const float4*)&wb[cw][(u + 1) & 1][4];
                float4 v2 = *(const float4*)&wb[cw][(u + 1) & 1][8];
                float4 v3 = *(const float4*)&wb[cw][(u + 1) & 1][12];
                float v16 = wb[cw][(u + 1) & 1][16];
                float a0 = v0.x * E0, a1 = v0.y * E1, a2 = v0.z * E2, a3 = v0.w * E3;
                float a4 = v1.x * E4, a5 = v1.y * E5, a6 = v1.z * E6, a7 = v1.w * E7;
                a0 = fmaf(v2.x, E8, a0);  a1 = fmaf(v2.y, E9, a1);
                a2 = fmaf(v2.z, E10, a2); a3 = fmaf(v2.w, E11, a3);
                a4 = fmaf(v3.x, E12, a4); a5 = fmaf(v3.y, E13, a5);
                a6 = fmaf(v3.z, E14, a6); a7 = fmaf(v3.w, E15, a7);
                a0 = fmaf(v16, E16, a0);
                float wn = ew[u] * (((a0 + a1) + (a2 + a3)) + ((a4 + a5) + (a6 + a7)));
                w = (mA[u] > 0) ? wn : w;
                if (u == 7) {            // free renorm via prev step's w[0]
                    float sc = v0.x;
                    w *= __frcp_rn(sc);
                    l2 += (double)__log2f(sc);
                }
                if (act) wb[cw][u & 1][j] = w;
            }
#pragma unroll
            for (int u = 0; u < 8; u++) {
                ew[u] = __expf(rB[u]);
                rA[u] = rB[u]; mA[u] = mB[u];
                rB[u] = rC[u]; mB[u] = mC[u];
            }
        }
        if (act) s_vec[cw][j] = w;
        if (j == 0) { s_l2[cw] = l2; if (cw == 0) s_s0 = s0; }
    } else if (wid < 4) {
        // ============ BACKWARD chain: cw=2 seg2 [1359..680], cw=3 seg3 [2047..1360]
        int cw = wid;
        int thi = (cw == 2) ? 1359 : 2047;
        int tlo = (cw == 2) ? 680 : 1360;
        int tbA = thi - 7;
        float F0  = act ? g_E[j * Nn + 0]  : 0.f, F1  = act ? g_E[j * Nn + 1]  : 0.f;
        float F2  = act ? g_E[j * Nn + 2]  : 0.f, F3  = act ? g_E[j * Nn + 3]  : 0.f;
        float F4  = act ? g_E[j * Nn + 4]  : 0.f, F5  = act ? g_E[j * Nn + 5]  : 0.f;
        float F6  = act ? g_E[j * Nn + 6]  : 0.f, F7  = act ? g_E[j * Nn + 7]  : 0.f;
        float F8  = act ? g_E[j * Nn + 8]  : 0.f, F9  = act ? g_E[j * Nn + 9]  : 0.f;
        float F10 = act ? g_E[j * Nn + 10] : 0.f, F11 = act ? g_E[j * Nn + 11] : 0.f;
        float F12 = act ? g_E[j * Nn + 12] : 0.f, F13 = act ? g_E[j * Nn + 13] : 0.f;
        float F14 = act ? g_E[j * Nn + 14] : 0.f, F15 = act ? g_E[j * Nn + 15] : 0.f;
        float F16 = act ? g_E[j * Nn + 16] : 0.f;

        float rA[8], rB[8], rC[8];
        int mA[8], mB[8], mC[8];
        float ew[8];
#pragma unroll
        for (int u = 0; u < 8; u++) {
            rA[u] = act ? __ldg(inp + (size_t)(tbA + u) * Nn + j) : 0.f;
            mA[u] = __ldg(mkp + tbA + u);
            rB[u] = act ? __ldg(inp + (size_t)(tbA - 8 + u) * Nn + j) : 0.f;
            mB[u] = __ldg(mkp + tbA - 8 + u);
            rC[u] = 0.f; mC[u] = 0;
        }
#pragma unroll
        for (int u = 0; u < 8; u++) ew[u] = __expf(rA[u]);

        float ur = act ? 1.f : 0.f;
        double l2 = 0.0;

        for (int tb = tbA; tb >= tlo; tb -= 8) {
            if (tb - 16 >= tlo) {
                int tp = tb - 16;
#pragma unroll
                for (int u = 0; u < 8; u++) {
                    rC[u] = act ? __ldg(inp + (size_t)(tp + u) * Nn + j) : 0.f;
                    mC[u] = __ldg(mkp + tp + u);
                }
            }
#pragma unroll
            for (int u = 7; u >= 0; u--) {
                float z = ew[u] * ur;
                if (act) wb[cw][u & 1][j] = z;
                __syncwarp();
                float4 v0 = *(const float4*)&wb[cw][u & 1][0];
                float4 v1 = *(const float4*)&wb[cw][u & 1][4];
                float4 v2 = *(const float4*)&wb[cw][u & 1][8];
                float4 v3 = *(const float4*)&wb[cw][u & 1][12];
                float v16 = wb[cw][u & 1][16];
                float a0 = v0.x * F0, a1 = v0.y * F1, a2 = v0.z * F2, a3 = v0.w * F3;
                float a4 = v1.x * F4, a5 = v1.y * F5, a6 = v1.z * F6, a7 = v1.w * F7;
                a0 = fmaf(v2.x, F8, a0);  a1 = fmaf(v2.y, F9, a1);
                a2 = fmaf(v2.z, F10, a2); a3 = fmaf(v2.w, F11, a3);
                a4 = fmaf(v3.x, F12, a4); a5 = fmaf(v3.y, F13, a5);
                a6 = fmaf(v3.z, F14, a6); a7 = fmaf(v3.w, F15, a7);
                a0 = fmaf(v16, F16, a0);
                float cand = ((a0 + a1) + (a2 + a3)) + ((a4 + a5) + (a6 + a7));
                ur = (mA[u] > 0) ? cand : ur;
                if (u == 0) {
                    float sc = v0.x;
                    ur *= __frcp_rn(sc);
                    l2 += (double)__log2f(sc);
                }
            }
#pragma unroll
            for (int u = 0; u < 8; u++) {
                ew[u] = __expf(rB[u]);
                rA[u] = rB[u]; mA[u] = mB[u];
                rB[u] = rC[u]; mB[u] = mC[u];
            }
        }
        if (act) s_vec[cw][j] = ur;
        if (j == 0) s_l2[cw] = l2;
    } else {
        // ===================== NUMERATOR =====================
        float tr_acc = 0.f, em_acc = 0.f;
        int cnt = 0;
        for (int t = j; t < Tn - 1; t += 32) {
            int tg0 = __ldg(tgp + t), tg1 = __ldg(tgp + t + 1);
            int mk0 = __ldg(mkp + t), mk1 = __ldg(mkp + t + 1);
            float ev = __ldg(inp + (size_t)t * Nn + tg0);
            tr_acc = fmaf(s_tr[tg0 * Nn + tg1], (float)mk1, tr_acc);
            em_acc = fmaf(ev, (float)mk0, em_acc);
            cnt += mk0;
        }
#pragma unroll
        for (int off = 16; off; off >>= 1) {
            tr_acc += __shfl_xor_sync(FULL, tr_acc, off);
            em_acc += __shfl_xor_sync(FULL, em_acc, off);
            cnt += __shfl_xor_sync(FULL, cnt, off);
        }
        if (j == 0) {
            int mkL = __ldg(mkp + Tn - 1);
            cnt += mkL;
            int li = cnt - 1; if (li < 0) li = 0;
            int tagL = __ldg(tgp + li);
            float evL = __ldg(inp + (size_t)(Tn - 1) * Nn + tagL) * (float)mkL;
            s_num = tr_acc + em_acc + evL;
        }
    }
    __syncthreads();

    if (wid == 0) {
        // ---- combine: den = s0 + ln2(La1+Lb2+Lb3) + ln(b2.a1)+ln(b3.a2)-ln(sum a2)
        float d1 = act ? s_vec[2][j] * s_vec[0][j] : 0.f;   // b2 . a1
        float d2 = act ? s_vec[3][j] * s_vec[1][j] : 0.f;   // b3 . a2
        float m2 = act ? s_vec[1][j] : 0.f;                  // sum a2
#pragma unroll
        for (int off = 16; off; off >>= 1) {
            d1 += __shfl_xor_sync(FULL, d1, off);
            d2 += __shfl_xor_sync(FULL, d2, off);
            m2 += __shfl_xor_sync(FULL, m2, off);
        }
        if (j == 0) {
            // a2's scale cancels between d2 and m2; only La1, Lb2, Lb3 survive.
            double l2t = s_l2[0] + s_l2[2] + s_l2[3];
            double den = (double)s_s0 + 0.6931471805599453 * l2t
                       + log((double)d1) + log((double)d2) - log((double)m2);
            g_scratch[b] = (float)((double)s_num - den);
            __threadfence();
        }
        int flag = 0;
        if (j == 0) {
            int ticket = atomicAdd(&g_done, 1);
            flag = (ticket == Bn - 1);
        }
        flag = __shfl_sync(FULL, flag, 0);
        if (flag) {
            __threadfence();
            volatile float* gs = g_scratch;
            double acc = 0.0;
#pragma unroll
            for (int k = 0; k < Bn / 32; k++) acc += (double)gs[j + k * 32];
#pragma unroll
            for (int off = 16; off; off >>= 1) acc += __shfl_xor_sync(FULL, acc, off);
            if (j == 0) out[0] = (float)acc;
        }
    }
}

extern "C" void kernel_launch(void* const* d_in, const int* in_sizes, int n_in,
                              void* d_out, int out_size) {
    const float* inputs     = (const float*)d_in[0];
    const int*   tags       = (const int*)d_in[1];
    const float* hiddens    = (const float*)d_in[2];
    const int*   mask       = (const int*)d_in[3];
    const float* p_in       = (const float*)d_in[4];
    const float* p_cross    = (const float*)d_in[5];
    const float* p_out      = (const float*)d_in[6];
    const float* p_to_out   = (const float*)d_in[7];
    const float* p_from_out = (const float*)d_in[8];
    const float* w_attn     = (const float*)d_in[9];
    const float* b_attn     = (const float*)d_in[10];

    k_build<<<1, 1024>>>(hiddens, p_in, p_cross, p_out, p_to_out, p_from_out,
                         w_attn, b_attn);
    k_scan<<<Bn, 160>>>(inputs, tags, mask, (float*)d_out);
}